// round 1
// baseline (speedup 1.0000x reference)
#include <cuda_runtime.h>
#include <cstdint>

#define DIM      512
#define KTOP     5
#define NTHREADS 512
#define NWARPS   (NTHREADS / 32)

// Tie-break identical to jax.lax.top_k: higher value first, then lower index.
__device__ __forceinline__ bool better(float av, int ai, float bv, int bi) {
    return (av > bv) || (av == bv && ai < bi);
}

// Insert (nv, ni) into a descending-sorted top-5 list held in registers.
__device__ __forceinline__ void insert5(float (&v)[KTOP], int (&ix)[KTOP],
                                        float nv, int ni) {
    if (!better(nv, ni, v[KTOP - 1], ix[KTOP - 1])) return;
    v[KTOP - 1] = nv;
    ix[KTOP - 1] = ni;
#pragma unroll
    for (int j = KTOP - 1; j > 0; --j) {
        if (better(v[j], ix[j], v[j - 1], ix[j - 1])) {
            float tv = v[j]; v[j] = v[j - 1]; v[j - 1] = tv;
            int   ti = ix[j]; ix[j] = ix[j - 1]; ix[j - 1] = ti;
        } else {
            break;
        }
    }
}

// Merge partner lane's top-5 list into ours via xor-shuffle butterfly step.
__device__ __forceinline__ void warp_merge_step(float (&v)[KTOP], int (&ix)[KTOP],
                                                int off) {
    float ov[KTOP];
    int   oi[KTOP];
#pragma unroll
    for (int j = 0; j < KTOP; ++j) {
        ov[j] = __shfl_xor_sync(0xFFFFFFFFu, v[j], off);
        oi[j] = __shfl_xor_sync(0xFFFFFFFFu, ix[j], off);
    }
#pragma unroll
    for (int j = 0; j < KTOP; ++j) insert5(v, ix, ov[j], oi[j]);
}

__global__ __launch_bounds__(NTHREADS)
void fused_topk_attn_kernel(const float* __restrict__ sp_z,
                            const float* __restrict__ sp_w,
                            const float* __restrict__ encoded,
                            float* __restrict__ out,       // [B, DIM]
                            float* __restrict__ attn_out,  // [B, KTOP] or nullptr
                            float* __restrict__ idx_out,   // [B, KTOP] or nullptr
                            int V) {
    const int row  = blockIdx.x;
    const int tid  = threadIdx.x;
    const int lane = tid & 31;
    const int warp = tid >> 5;

    __shared__ float s_wv[NWARPS][KTOP];
    __shared__ int   s_wi[NWARPS][KTOP];
    __shared__ float s_val[KTOP];
    __shared__ int   s_idx[KTOP];
    __shared__ float s_red[NWARPS][KTOP];
    __shared__ float s_scores[KTOP];

    // ---------------- Phase 1: per-row top-5 of sp_z[row, :] ----------------
    float v[KTOP];
    int   ix[KTOP];
#pragma unroll
    for (int k = 0; k < KTOP; ++k) { v[k] = -__int_as_float(0x7F800000); ix[k] = 0x7FFFFFFF; }

    const size_t rowbase = (size_t)row * (size_t)V;

    if ((V & 3) == 0) {
        const float4* zrow = reinterpret_cast<const float4*>(sp_z + rowbase);
        const int nv4 = V >> 2;
        for (int i = tid; i < nv4; i += NTHREADS) {
            float4 z = __ldg(zrow + i);
            int base = i << 2;
            insert5(v, ix, z.x, base);
            insert5(v, ix, z.y, base + 1);
            insert5(v, ix, z.z, base + 2);
            insert5(v, ix, z.w, base + 3);
        }
    } else {
        for (int j = tid; j < V; j += NTHREADS)
            insert5(v, ix, __ldg(sp_z + rowbase + j), j);
    }

    // Warp-level butterfly merge: every lane ends with the warp's top-5.
#pragma unroll
    for (int off = 16; off; off >>= 1) warp_merge_step(v, ix, off);

    if (lane == 0) {
#pragma unroll
        for (int k = 0; k < KTOP; ++k) { s_wv[warp][k] = v[k]; s_wi[warp][k] = ix[k]; }
    }
    __syncthreads();

    // Cross-warp merge in warp 0 (16 candidate lists on lanes 0..15).
    if (warp == 0) {
        float mv[KTOP];
        int   mi[KTOP];
        if (lane < NWARPS) {
#pragma unroll
            for (int k = 0; k < KTOP; ++k) { mv[k] = s_wv[lane][k]; mi[k] = s_wi[lane][k]; }
        } else {
#pragma unroll
            for (int k = 0; k < KTOP; ++k) { mv[k] = -__int_as_float(0x7F800000); mi[k] = 0x7FFFFFFF; }
        }
#pragma unroll
        for (int off = 8; off; off >>= 1) warp_merge_step(mv, mi, off);
        if (lane == 0) {
#pragma unroll
            for (int k = 0; k < KTOP; ++k) { s_val[k] = mv[k]; s_idx[k] = mi[k]; }
        }
    }
    __syncthreads();

    // ---------------- Phase 2: gather + attention ----------------
    // Thread tid owns output dimension d = tid (DIM == NTHREADS == 512).
    const int d = tid;
    const float enc = __ldg(encoded + (size_t)row * DIM + d);

    float w[KTOP];
    float partial[KTOP];
#pragma unroll
    for (int k = 0; k < KTOP; ++k) {
        w[k] = __ldg(sp_w + (size_t)s_idx[k] * DIM + d);
        partial[k] = w[k] * enc;
    }

    // Block reduction of the 5 dot products.
#pragma unroll
    for (int off = 16; off; off >>= 1) {
#pragma unroll
        for (int k = 0; k < KTOP; ++k)
            partial[k] += __shfl_down_sync(0xFFFFFFFFu, partial[k], off);
    }
    if (lane == 0) {
#pragma unroll
        for (int k = 0; k < KTOP; ++k) s_red[warp][k] = partial[k];
    }
    __syncthreads();
    if (tid < KTOP) {
        float s = 0.f;
#pragma unroll
        for (int wq = 0; wq < NWARPS; ++wq) s += s_red[wq][tid];
        s_scores[tid] = s;
    }
    __syncthreads();

    // Softmax over K=5, computed redundantly per thread (cheap, avoids a sync).
    float sc[KTOP];
#pragma unroll
    for (int k = 0; k < KTOP; ++k) sc[k] = s_scores[k];
    float m = sc[0];
#pragma unroll
    for (int k = 1; k < KTOP; ++k) m = fmaxf(m, sc[k]);
    float e[KTOP];
    float esum = 0.f;
#pragma unroll
    for (int k = 0; k < KTOP; ++k) { e[k] = expf(sc[k] - m); esum += e[k]; }
    const float inv = 1.0f / esum;

    float acc = 0.f;
#pragma unroll
    for (int k = 0; k < KTOP; ++k) acc += w[k] * (e[k] * inv);
    out[(size_t)row * DIM + d] = acc;

    if (tid < KTOP) {
        if (attn_out) attn_out[(size_t)row * KTOP + tid] = e[tid] * inv;
        if (idx_out)  idx_out[(size_t)row * KTOP + tid] = (float)s_idx[tid];
    }
}

extern "C" void kernel_launch(void* const* d_in, const int* in_sizes, int n_in,
                              void* d_out, int out_size) {
    const float* sp_z    = (const float*)d_in[0];  // [B, V]
    const float* sp_w    = (const float*)d_in[1];  // [V, DIM]
    const float* encoded = (const float*)d_in[2];  // [B, DIM]

    const int B = in_sizes[2] / DIM;
    const int V = in_sizes[0] / B;

    float* out = (float*)d_out;
    // Tuple output flattened in return order: out [B*DIM], attn [B*K], indices [B*K].
    float* attn_out = nullptr;
    float* idx_out  = nullptr;
    if (out_size >= B * (DIM + KTOP))     attn_out = out + (size_t)B * DIM;
    if (out_size >= B * (DIM + 2 * KTOP)) idx_out  = out + (size_t)B * (DIM + KTOP);

    fused_topk_attn_kernel<<<B, NTHREADS>>>(sp_z, sp_w, encoded,
                                            out, attn_out, idx_out, V);
}